// round 1
// baseline (speedup 1.0000x reference)
#include <cuda_runtime.h>

// ---------------------------------------------------------------------------
// Problem constants
//   B=4, S=2048, D1=512, D2=1024
//   stage1: QKV on [x;y] (16384 x 512), 8 attention batches of S=2048, E=512
//   stage2: QKV on temp (8192 x 1024), 4 attention batches of S=2048, E=1024
// ---------------------------------------------------------------------------

#define BM 128
#define BN 128
#define BKK 8
#define TM 8
#define TN 8

// Scratch (static device memory; allocation APIs are forbidden)
__device__ float g_Q1[8388608];   // 16384 x 512
__device__ float g_K1[8388608];
__device__ float g_V1[8388608];
__device__ float g_O1[8388608];
__device__ float g_T [8388608];   // 8192 x 1024
__device__ float g_Q2[8388608];
__device__ float g_K2[8388608];
__device__ float g_V2[8388608];
__device__ float g_S [33554432];  // max(8,4) batches x 2048 x 2048

// ---------------------------------------------------------------------------
// NT GEMM: C[M,N] = A[M,K] * B[N,K]^T (+ bias[N]); row-major, K contiguous
// Batched via blockIdx.z with element strides sA/sB/sC.
// ---------------------------------------------------------------------------
__global__ void __launch_bounds__(256, 2)
gemm_nt(const float* __restrict__ A, const float* __restrict__ B,
        const float* __restrict__ bias, float* __restrict__ C,
        int M, int N, int K,
        long long sA, long long sB, long long sC)
{
    A += (long long)blockIdx.z * sA;
    B += (long long)blockIdx.z * sB;
    C += (long long)blockIdx.z * sC;

    __shared__ float As[BKK][BM];
    __shared__ float Bs[BKK][BN];

    const int tid = threadIdx.x;
    const int m0 = blockIdx.y * BM;
    const int n0 = blockIdx.x * BN;

    const int lrow = tid >> 1;         // 0..127
    const int lk   = (tid & 1) << 2;   // 0 or 4

    const float* Ap = A + (long long)(m0 + lrow) * K + lk;
    const float* Bp = B + (long long)(n0 + lrow) * K + lk;

    const int tx = tid & 15;
    const int ty = tid >> 4;
    const int cm = ty * TM;
    const int cn = tx * TN;

    float acc[TM][TN];
#pragma unroll
    for (int i = 0; i < TM; i++)
#pragma unroll
        for (int j = 0; j < TN; j++) acc[i][j] = 0.f;

    for (int k0 = 0; k0 < K; k0 += BKK) {
        float4 av = *reinterpret_cast<const float4*>(Ap + k0);
        float4 bv = *reinterpret_cast<const float4*>(Bp + k0);
        As[lk + 0][lrow] = av.x; As[lk + 1][lrow] = av.y;
        As[lk + 2][lrow] = av.z; As[lk + 3][lrow] = av.w;
        Bs[lk + 0][lrow] = bv.x; Bs[lk + 1][lrow] = bv.y;
        Bs[lk + 2][lrow] = bv.z; Bs[lk + 3][lrow] = bv.w;
        __syncthreads();
#pragma unroll
        for (int k = 0; k < BKK; k++) {
            float ra[TM], rb[TN];
#pragma unroll
            for (int i = 0; i < TM; i++) ra[i] = As[k][cm + i];
#pragma unroll
            for (int j = 0; j < TN; j++) rb[j] = Bs[k][cn + j];
#pragma unroll
            for (int i = 0; i < TM; i++)
#pragma unroll
                for (int j = 0; j < TN; j++)
                    acc[i][j] = fmaf(ra[i], rb[j], acc[i][j]);
        }
        __syncthreads();
    }

#pragma unroll
    for (int i = 0; i < TM; i++) {
        long long crow = (long long)(m0 + cm + i) * N + n0 + cn;
#pragma unroll
        for (int j = 0; j < TN; j += 4) {
            float4 v;
            v.x = acc[i][j + 0]; v.y = acc[i][j + 1];
            v.z = acc[i][j + 2]; v.w = acc[i][j + 3];
            if (bias) {
                v.x += bias[n0 + cn + j + 0];
                v.y += bias[n0 + cn + j + 1];
                v.z += bias[n0 + cn + j + 2];
                v.w += bias[n0 + cn + j + 3];
            }
            *reinterpret_cast<float4*>(C + crow + j) = v;
        }
    }
}

// ---------------------------------------------------------------------------
// NN GEMM: C[M,N] = A[M,K] * B[K,N]; row-major. Batched via blockIdx.z.
// ---------------------------------------------------------------------------
__global__ void __launch_bounds__(256, 2)
gemm_nn(const float* __restrict__ A, const float* __restrict__ B,
        float* __restrict__ C,
        int M, int N, int K,
        long long sA, long long sB, long long sC)
{
    A += (long long)blockIdx.z * sA;
    B += (long long)blockIdx.z * sB;
    C += (long long)blockIdx.z * sC;

    __shared__ float As[BKK][BM];
    __shared__ float Bs[BKK][BN];

    const int tid = threadIdx.x;
    const int m0 = blockIdx.y * BM;
    const int n0 = blockIdx.x * BN;

    const int lrow = tid >> 1;
    const int lk   = (tid & 1) << 2;

    const int bk = tid >> 5;           // 0..7
    const int bn = (tid & 31) << 2;    // 0..124

    const float* Ap = A + (long long)(m0 + lrow) * K + lk;
    const float* Bp = B + (long long)bk * N + n0 + bn;

    const int tx = tid & 15;
    const int ty = tid >> 4;
    const int cm = ty * TM;
    const int cn = tx * TN;

    float acc[TM][TN];
#pragma unroll
    for (int i = 0; i < TM; i++)
#pragma unroll
        for (int j = 0; j < TN; j++) acc[i][j] = 0.f;

    for (int k0 = 0; k0 < K; k0 += BKK) {
        float4 av = *reinterpret_cast<const float4*>(Ap + k0);
        float4 bv = *reinterpret_cast<const float4*>(Bp + (long long)k0 * N);
        As[lk + 0][lrow] = av.x; As[lk + 1][lrow] = av.y;
        As[lk + 2][lrow] = av.z; As[lk + 3][lrow] = av.w;
        *reinterpret_cast<float4*>(&Bs[bk][bn]) = bv;
        __syncthreads();
#pragma unroll
        for (int k = 0; k < BKK; k++) {
            float ra[TM], rb[TN];
#pragma unroll
            for (int i = 0; i < TM; i++) ra[i] = As[k][cm + i];
#pragma unroll
            for (int j = 0; j < TN; j++) rb[j] = Bs[k][cn + j];
#pragma unroll
            for (int i = 0; i < TM; i++)
#pragma unroll
                for (int j = 0; j < TN; j++)
                    acc[i][j] = fmaf(ra[i], rb[j], acc[i][j]);
        }
        __syncthreads();
    }

#pragma unroll
    for (int i = 0; i < TM; i++) {
        long long crow = (long long)(m0 + cm + i) * N + n0 + cn;
#pragma unroll
        for (int j = 0; j < TN; j += 4) {
            float4 v;
            v.x = acc[i][j + 0]; v.y = acc[i][j + 1];
            v.z = acc[i][j + 2]; v.w = acc[i][j + 3];
            *reinterpret_cast<float4*>(C + crow + j) = v;
        }
    }
}

// ---------------------------------------------------------------------------
// Row softmax over 2048 columns. One block (256 threads) per row.
// ---------------------------------------------------------------------------
__global__ void __launch_bounds__(256)
softmax2048(float* __restrict__ S)
{
    float* p = S + (long long)blockIdx.x * 2048;
    const int t = threadIdx.x;

    float v[8];
#pragma unroll
    for (int i = 0; i < 8; i++) v[i] = p[t + i * 256];

    float m = v[0];
#pragma unroll
    for (int i = 1; i < 8; i++) m = fmaxf(m, v[i]);

    __shared__ float red[8];
#pragma unroll
    for (int o = 16; o > 0; o >>= 1) m = fmaxf(m, __shfl_xor_sync(0xffffffffu, m, o));
    if ((t & 31) == 0) red[t >> 5] = m;
    __syncthreads();
    if (t < 32) {
        float mm = (t < 8) ? red[t] : -3.4e38f;
#pragma unroll
        for (int o = 4; o > 0; o >>= 1) mm = fmaxf(mm, __shfl_xor_sync(0xffffffffu, mm, o));
        if (t == 0) red[0] = mm;
    }
    __syncthreads();
    m = red[0];
    __syncthreads();   // red is reused below

    float s = 0.f;
#pragma unroll
    for (int i = 0; i < 8; i++) { v[i] = __expf(v[i] - m); s += v[i]; }
#pragma unroll
    for (int o = 16; o > 0; o >>= 1) s += __shfl_xor_sync(0xffffffffu, s, o);
    if ((t & 31) == 0) red[t >> 5] = s;
    __syncthreads();
    if (t < 32) {
        float ss = (t < 8) ? red[t] : 0.f;
#pragma unroll
        for (int o = 4; o > 0; o >>= 1) ss += __shfl_xor_sync(0xffffffffu, ss, o);
        if (t == 0) red[0] = ss;
    }
    __syncthreads();
    const float inv = 1.f / red[0];
#pragma unroll
    for (int i = 0; i < 8; i++) p[t + i * 256] = v[i] * inv;
}

// ---------------------------------------------------------------------------
// temp[tok, 0:512]   = O1_x[tok] + y[tok] * w2
// temp[tok, 512:1024]= O1_y[tok] + x[tok] * w1      (tok in [0, 8192))
// ---------------------------------------------------------------------------
__global__ void __launch_bounds__(256)
build_temp(const float* __restrict__ O1,
           const float* __restrict__ x, const float* __restrict__ y,
           const float* __restrict__ w1, const float* __restrict__ w2,
           float* __restrict__ T)
{
    long long i = (long long)blockIdx.x * 256 + threadIdx.x;  // < 8192*1024
    int col = (int)(i & 1023);
    long long tok = i >> 10;
    if (col < 512) {
        T[i] = O1[tok * 512 + col] + y[tok * 512 + col] * w2[0];
    } else {
        int c = col - 512;
        T[i] = O1[(8192 + tok) * 512 + c] + x[tok * 512 + c] * w1[0];
    }
}

// ---------------------------------------------------------------------------
extern "C" void kernel_launch(void* const* d_in, const int* in_sizes, int n_in,
                              void* d_out, int out_size)
{
    (void)in_sizes; (void)n_in; (void)out_size;

    const float* x    = (const float*)d_in[0];
    const float* y    = (const float*)d_in[1];
    const float* Wq1  = (const float*)d_in[2];
    const float* bq1  = (const float*)d_in[3];
    const float* Wk1  = (const float*)d_in[4];
    const float* bk1  = (const float*)d_in[5];
    const float* Wv1  = (const float*)d_in[6];
    const float* bv1  = (const float*)d_in[7];
    const float* Wq2  = (const float*)d_in[8];
    const float* bq2  = (const float*)d_in[9];
    const float* Wk2  = (const float*)d_in[10];
    const float* bk2  = (const float*)d_in[11];
    const float* Wv2  = (const float*)d_in[12];
    const float* bv2  = (const float*)d_in[13];
    const float* w1   = (const float*)d_in[14];
    const float* w2   = (const float*)d_in[15];
    float* out = (float*)d_out;

    float *Q1, *K1, *V1, *O1, *T, *Q2, *K2, *V2, *S;
    cudaGetSymbolAddress((void**)&Q1, g_Q1);
    cudaGetSymbolAddress((void**)&K1, g_K1);
    cudaGetSymbolAddress((void**)&V1, g_V1);
    cudaGetSymbolAddress((void**)&O1, g_O1);
    cudaGetSymbolAddress((void**)&T,  g_T);
    cudaGetSymbolAddress((void**)&Q2, g_Q2);
    cudaGetSymbolAddress((void**)&K2, g_K2);
    cudaGetSymbolAddress((void**)&V2, g_V2);
    cudaGetSymbolAddress((void**)&S,  g_S);

    const dim3 blk(256);
    const long long HALF = 8192LL * 512;   // token-rows per half in stage-1 QKV

    // --- Stage 1: QKV projections (shared sa1 weights for x and y) ---------
    dim3 g1(512 / BN, 8192 / BM);
    gemm_nt<<<g1, blk>>>(x, Wq1, bq1, Q1,        8192, 512, 512, 0, 0, 0);
    gemm_nt<<<g1, blk>>>(y, Wq1, bq1, Q1 + HALF, 8192, 512, 512, 0, 0, 0);
    gemm_nt<<<g1, blk>>>(x, Wk1, bk1, K1,        8192, 512, 512, 0, 0, 0);
    gemm_nt<<<g1, blk>>>(y, Wk1, bk1, K1 + HALF, 8192, 512, 512, 0, 0, 0);
    gemm_nt<<<g1, blk>>>(x, Wv1, bv1, V1,        8192, 512, 512, 0, 0, 0);
    gemm_nt<<<g1, blk>>>(y, Wv1, bv1, V1 + HALF, 8192, 512, 512, 0, 0, 0);

    // --- Stage 1: scores = Q K^T over 8 batches, softmax, P V --------------
    dim3 gs1(2048 / BN, 2048 / BM, 8);
    gemm_nt<<<gs1, blk>>>(Q1, K1, nullptr, S, 2048, 2048, 512,
                          2048LL * 512, 2048LL * 512, 2048LL * 2048);
    softmax2048<<<16384, 256>>>(S);
    dim3 gp1(512 / BN, 2048 / BM, 8);
    gemm_nn<<<gp1, blk>>>(S, V1, O1, 2048, 512, 2048,
                          2048LL * 2048, 2048LL * 512, 2048LL * 512);

    // --- Build temp = concat(x1 + y*w2, y1 + x*w1) -------------------------
    build_temp<<<(8192 * 1024) / 256, 256>>>(O1, x, y, w1, w2, T);

    // --- Stage 2: QKV projections ------------------------------------------
    dim3 g2(1024 / BN, 8192 / BM);
    gemm_nt<<<g2, blk>>>(T, Wq2, bq2, Q2, 8192, 1024, 1024, 0, 0, 0);
    gemm_nt<<<g2, blk>>>(T, Wk2, bk2, K2, 8192, 1024, 1024, 0, 0, 0);
    gemm_nt<<<g2, blk>>>(T, Wv2, bv2, V2, 8192, 1024, 1024, 0, 0, 0);

    // --- Stage 2: scores over 4 batches, softmax, P V -> out ---------------
    dim3 gs2(2048 / BN, 2048 / BM, 4);
    gemm_nt<<<gs2, blk>>>(Q2, K2, nullptr, S, 2048, 2048, 1024,
                          2048LL * 1024, 2048LL * 1024, 2048LL * 2048);
    softmax2048<<<8192, 256>>>(S);
    dim3 gp2(1024 / BN, 2048 / BM, 4);
    gemm_nn<<<gp2, blk>>>(S, V2, out, 2048, 1024, 2048,
                          2048LL * 2048, 2048LL * 1024, 2048LL * 1024);
}

// round 3
// speedup vs baseline: 1.8448x; 1.8448x over previous
#include <cuda_runtime.h>
#include <cuda_bf16.h>
#include <cstdint>

// ===========================================================================
// Cross-attention, all GEMMs via mma.sync bf16 split-precision x3 (fp32 acc).
//   Block tile 128x128, 8 warps (warp tile 64x32), K-chunk 32, double buffer.
//   PTX target is plain compute_103 -> tcgen05 unavailable; HMMA path instead.
// ===========================================================================

#define ROWB 80  // smem bytes per 32-bf16 row (64B data + 16B pad, LDSM-friendly)

// ---------------- helpers ----------------
__device__ __forceinline__ uint32_t smem_u32(const void* p) {
    uint32_t a;
    asm("{ .reg .u64 t; cvta.to.shared.u64 t, %1; cvt.u32.u64 %0, t; }"
        : "=r"(a) : "l"(p));
    return a;
}
__device__ __forceinline__ void ldsm_x4(uint32_t* r, uint32_t addr) {
    asm volatile("ldmatrix.sync.aligned.m8n8.x4.shared.b16 {%0,%1,%2,%3}, [%4];"
                 : "=r"(r[0]), "=r"(r[1]), "=r"(r[2]), "=r"(r[3]) : "r"(addr));
}
__device__ __forceinline__ void mma16816(float* d, const uint32_t* a,
                                         uint32_t b0, uint32_t b1) {
    asm volatile(
        "mma.sync.aligned.m16n8k16.row.col.f32.bf16.bf16.f32 "
        "{%0,%1,%2,%3}, {%4,%5,%6,%7}, {%8,%9}, {%0,%1,%2,%3};"
        : "+f"(d[0]), "+f"(d[1]), "+f"(d[2]), "+f"(d[3])
        : "r"(a[0]), "r"(a[1]), "r"(a[2]), "r"(a[3]), "r"(b0), "r"(b1));
}
__device__ __forceinline__ void split4(float4 v, uint2& h, uint2& l) {
    __nv_bfloat16 h0 = __float2bfloat16(v.x);
    __nv_bfloat16 h1 = __float2bfloat16(v.y);
    __nv_bfloat16 h2 = __float2bfloat16(v.z);
    __nv_bfloat16 h3 = __float2bfloat16(v.w);
    __nv_bfloat16 l0 = __float2bfloat16(v.x - __bfloat162float(h0));
    __nv_bfloat16 l1 = __float2bfloat16(v.y - __bfloat162float(h1));
    __nv_bfloat16 l2 = __float2bfloat16(v.z - __bfloat162float(h2));
    __nv_bfloat16 l3 = __float2bfloat16(v.w - __bfloat162float(h3));
    __nv_bfloat162 ph0(h0, h1), ph1(h2, h3), pl0(l0, l1), pl1(l2, l3);
    h.x = *reinterpret_cast<uint32_t*>(&ph0);
    h.y = *reinterpret_cast<uint32_t*>(&ph1);
    l.x = *reinterpret_cast<uint32_t*>(&pl0);
    l.y = *reinterpret_cast<uint32_t*>(&pl1);
}

// ---------------- scratch (static device memory) ----------------
__device__ float g_Q1[16384LL * 512];
__device__ float g_K1[16384LL * 512];
__device__ float g_VT1[16384LL * 512];   // [8][512][2048]
__device__ float g_O1[16384LL * 512];
__device__ float g_T [8192LL * 1024];
__device__ float g_Q2[8192LL * 1024];
__device__ float g_K2[8192LL * 1024];
__device__ float g_VT2[8192LL * 1024];   // [4][1024][2048]
__device__ float g_S [8LL * 2048 * 2048];

// SMEM: buffer s base = s*40960; aHi +0, aLo +10240, bHi +20480, bLo +30720
static constexpr int SMEM_BYTES = 81920;

// ===========================================================================
// NT GEMM: C[M,N] = A[M,K] * B[N,K]^T (+bias). fp32 in/out, bf16x3 HMMA.
//   transposed=0: C[row*N+col], batched by blockIdx.z*sC
//   transposed=1: C[(row>>11)*ntot*2048 + col*2048 + (row&2047)]   (VT layout)
// Requires M%128==0, N%128==0, K%32==0; ldA=ldB=K; ldC=N.
// ===========================================================================
__global__ void __launch_bounds__(256, 1)
gemm_tc(const float* __restrict__ A, const float* __restrict__ B,
        const float* __restrict__ bias, float* __restrict__ C,
        int M, int N, int K,
        long long sA, long long sB, long long sC,
        int transposed, int ntot)
{
    extern __shared__ char smem[];
    const uint32_t sb = smem_u32(smem);
    const int tid = threadIdx.x;
    const int lane = tid & 31;
    const int wid = tid >> 5;

    A += (long long)blockIdx.z * sA;
    B += (long long)blockIdx.z * sB;
    if (!transposed) C += (long long)blockIdx.z * sC;

    const int m0 = blockIdx.y * 128;
    const int n0 = blockIdx.x * 128;
    const int m0w = (wid & 1) * 64;
    const int n0w = (wid >> 1) * 32;

    const int lrow = tid >> 3;          // 0..31
    const int lc4 = (tid & 7) * 4;      // fp32 col 0..28

    float acc[4][4][4];
#pragma unroll
    for (int i = 0; i < 4; i++)
#pragma unroll
        for (int j = 0; j < 4; j++)
#pragma unroll
            for (int k = 0; k < 4; k++) acc[i][j][k] = 0.f;

    const float* Ag = A + (long long)(m0 + lrow) * K + lc4;
    const float* Bg = B + (long long)(n0 + lrow) * K + lc4;

    float4 ra[4], rb[4];
#pragma unroll
    for (int i = 0; i < 4; i++) {
        ra[i] = *reinterpret_cast<const float4*>(Ag + (long long)i * 32 * K);
        rb[i] = *reinterpret_cast<const float4*>(Bg + (long long)i * 32 * K);
    }
    // store chunk 0 into buffer 0
    {
        char* aH = smem;           char* aL = smem + 10240;
        char* bH = smem + 20480;   char* bL = smem + 30720;
#pragma unroll
        for (int i = 0; i < 4; i++) {
            const uint32_t off = (uint32_t)(lrow + 32 * i) * ROWB + (uint32_t)lc4 * 2;
            uint2 h, l;
            split4(ra[i], h, l);
            *reinterpret_cast<uint2*>(aH + off) = h;
            *reinterpret_cast<uint2*>(aL + off) = l;
            split4(rb[i], h, l);
            *reinterpret_cast<uint2*>(bH + off) = h;
            *reinterpret_cast<uint2*>(bL + off) = l;
        }
    }
    __syncthreads();

    const int nch = K >> 5;
    for (int ch = 0; ch < nch; ch++) {
        const int s = ch & 1;
        if (ch + 1 < nch) {
            const float* Ap = Ag + (ch + 1) * 32;
            const float* Bp = Bg + (ch + 1) * 32;
#pragma unroll
            for (int i = 0; i < 4; i++) {
                ra[i] = *reinterpret_cast<const float4*>(Ap + (long long)i * 32 * K);
                rb[i] = *reinterpret_cast<const float4*>(Bp + (long long)i * 32 * K);
            }
        }

        // ---- compute chunk ch from buffer s ----
        {
            const uint32_t base = sb + (uint32_t)s * 40960;
            const uint32_t aHiB = base, aLoB = base + 10240;
            const uint32_t bHiB = base + 20480, bLoB = base + 30720;
            const uint32_t arow = (uint32_t)(m0w + (lane & 15)) * ROWB;
            const uint32_t brow = (uint32_t)(n0w + (lane & 15)) * ROWB;
#pragma unroll
            for (int kstep = 0; kstep < 2; kstep++) {
                const uint32_t kb = (uint32_t)(kstep * 2 + (lane >> 4)) * 16;
                uint32_t aH[4][4], aL[4][4];
#pragma unroll
                for (int mf = 0; mf < 4; mf++) {
                    ldsm_x4(aH[mf], aHiB + arow + (uint32_t)mf * (16 * ROWB) + kb);
                    ldsm_x4(aL[mf], aLoB + arow + (uint32_t)mf * (16 * ROWB) + kb);
                }
                uint32_t bh[2][4], bl[2][4];
#pragma unroll
                for (int q = 0; q < 2; q++) {
                    ldsm_x4(bh[q], bHiB + brow + (uint32_t)q * (16 * ROWB) + kb);
                    ldsm_x4(bl[q], bLoB + brow + (uint32_t)q * (16 * ROWB) + kb);
                }
#pragma unroll
                for (int mf = 0; mf < 4; mf++)
#pragma unroll
                    for (int nf = 0; nf < 4; nf++) {
                        const uint32_t b0h = bh[nf >> 1][nf & 1];
                        const uint32_t b1h = bh[nf >> 1][(nf & 1) + 2];
                        const uint32_t b0l = bl[nf >> 1][nf & 1];
                        const uint32_t b1l = bl[nf >> 1][(nf & 1) + 2];
                        mma16816(acc[mf][nf], aH[mf], b0h, b1h);
                        mma16816(acc[mf][nf], aH[mf], b0l, b1l);
                        mma16816(acc[mf][nf], aL[mf], b0h, b1h);
                    }
            }
        }
        __syncthreads();

        if (ch + 1 < nch) {
            char* dst = smem + (s ^ 1) * 40960;
            char* aH = dst;          char* aL = dst + 10240;
            char* bH = dst + 20480;  char* bL = dst + 30720;
#pragma unroll
            for (int i = 0; i < 4; i++) {
                const uint32_t off = (uint32_t)(lrow + 32 * i) * ROWB + (uint32_t)lc4 * 2;
                uint2 h, l;
                split4(ra[i], h, l);
                *reinterpret_cast<uint2*>(aH + off) = h;
                *reinterpret_cast<uint2*>(aL + off) = l;
                split4(rb[i], h, l);
                *reinterpret_cast<uint2*>(bH + off) = h;
                *reinterpret_cast<uint2*>(bL + off) = l;
            }
            __syncthreads();
        }
    }

    // ---- epilogue ----
    const int gr = lane >> 2;
    const int gc = (lane & 3) * 2;

    if (!transposed) {
#pragma unroll
        for (int mf = 0; mf < 4; mf++)
#pragma unroll
            for (int nf = 0; nf < 4; nf++) {
                const int row = m0 + m0w + mf * 16 + gr;
                const int col = n0 + n0w + nf * 8 + gc;
                float b0 = 0.f, b1 = 0.f;
                if (bias) { b0 = bias[col]; b1 = bias[col + 1]; }
                float2 v0 = make_float2(acc[mf][nf][0] + b0, acc[mf][nf][1] + b1);
                float2 v1 = make_float2(acc[mf][nf][2] + b0, acc[mf][nf][3] + b1);
                *reinterpret_cast<float2*>(C + (long long)row * N + col) = v0;
                *reinterpret_cast<float2*>(C + (long long)(row + 8) * N + col) = v1;
            }
    } else {
        __syncthreads();  // done reading mainloop smem
        float* tw = reinterpret_cast<float*>(smem) + wid * 2080;
#pragma unroll
        for (int mf = 0; mf < 4; mf++)
#pragma unroll
            for (int nf = 0; nf < 4; nf++) {
                const int rl = mf * 16 + gr;
                const int cl = nf * 8 + gc;
                tw[cl * 65 + rl]           = acc[mf][nf][0];
                tw[(cl + 1) * 65 + rl]     = acc[mf][nf][1];
                tw[cl * 65 + rl + 8]       = acc[mf][nf][2];
                tw[(cl + 1) * 65 + rl + 8] = acc[mf][nf][3];
            }
        __syncwarp();
        const int g0 = m0 + m0w;
        const long long basev =
            (long long)(g0 >> 11) * ntot * 2048 + (g0 & 2047);
#pragma unroll 4
        for (int c = 0; c < 32; c++) {
            const int colg = n0 + n0w + c;
            const float bb = bias ? bias[colg] : 0.f;
            float2 v;
            v.x = tw[c * 65 + lane * 2] + bb;
            v.y = tw[c * 65 + lane * 2 + 1] + bb;
            *reinterpret_cast<float2*>(C + basev + (long long)colg * 2048 + lane * 2) = v;
        }
    }
}

// ---------------------------------------------------------------------------
// Row softmax over 2048 columns. One block (256 threads) per row.
// ---------------------------------------------------------------------------
__global__ void __launch_bounds__(256)
softmax2048(float* __restrict__ S)
{
    float* p = S + (long long)blockIdx.x * 2048;
    const int t = threadIdx.x;

    float v[8];
#pragma unroll
    for (int i = 0; i < 8; i++) v[i] = p[t + i * 256];

    float m = v[0];
#pragma unroll
    for (int i = 1; i < 8; i++) m = fmaxf(m, v[i]);

    __shared__ float red[8];
#pragma unroll
    for (int o = 16; o > 0; o >>= 1) m = fmaxf(m, __shfl_xor_sync(0xffffffffu, m, o));
    if ((t & 31) == 0) red[t >> 5] = m;
    __syncthreads();
    if (t < 32) {
        float mm = (t < 8) ? red[t] : -3.4e38f;
#pragma unroll
        for (int o = 4; o > 0; o >>= 1) mm = fmaxf(mm, __shfl_xor_sync(0xffffffffu, mm, o));
        if (t == 0) red[0] = mm;
    }
    __syncthreads();
    m = red[0];
    __syncthreads();

    float s = 0.f;
#pragma unroll
    for (int i = 0; i < 8; i++) { v[i] = __expf(v[i] - m); s += v[i]; }
#pragma unroll
    for (int o = 16; o > 0; o >>= 1) s += __shfl_xor_sync(0xffffffffu, s, o);
    if ((t & 31) == 0) red[t >> 5] = s;
    __syncthreads();
    if (t < 32) {
        float ss = (t < 8) ? red[t] : 0.f;
#pragma unroll
        for (int o = 4; o > 0; o >>= 1) ss += __shfl_xor_sync(0xffffffffu, ss, o);
        if (t == 0) red[0] = ss;
    }
    __syncthreads();
    const float inv = 1.f / red[0];
#pragma unroll
    for (int i = 0; i < 8; i++) p[t + i * 256] = v[i] * inv;
}

// ---------------------------------------------------------------------------
__global__ void __launch_bounds__(256)
build_temp(const float* __restrict__ O1,
           const float* __restrict__ x, const float* __restrict__ y,
           const float* __restrict__ w1, const float* __restrict__ w2,
           float* __restrict__ T)
{
    long long i = (long long)blockIdx.x * 256 + threadIdx.x;
    int col = (int)(i & 1023);
    long long tok = i >> 10;
    if (col < 512) {
        T[i] = O1[tok * 512 + col] + y[tok * 512 + col] * w2[0];
    } else {
        int c = col - 512;
        T[i] = O1[(8192 + tok) * 512 + c] + x[tok * 512 + c] * w1[0];
    }
}

// ---------------------------------------------------------------------------
extern "C" void kernel_launch(void* const* d_in, const int* in_sizes, int n_in,
                              void* d_out, int out_size)
{
    (void)in_sizes; (void)n_in; (void)out_size;

    const float* x   = (const float*)d_in[0];
    const float* y   = (const float*)d_in[1];
    const float* Wq1 = (const float*)d_in[2];
    const float* bq1 = (const float*)d_in[3];
    const float* Wk1 = (const float*)d_in[4];
    const float* bk1 = (const float*)d_in[5];
    const float* Wv1 = (const float*)d_in[6];
    const float* bv1 = (const float*)d_in[7];
    const float* Wq2 = (const float*)d_in[8];
    const float* bq2 = (const float*)d_in[9];
    const float* Wk2 = (const float*)d_in[10];
    const float* bk2 = (const float*)d_in[11];
    const float* Wv2 = (const float*)d_in[12];
    const float* bv2 = (const float*)d_in[13];
    const float* w1  = (const float*)d_in[14];
    const float* w2  = (const float*)d_in[15];
    float* out = (float*)d_out;

    float *Q1, *K1, *VT1, *O1, *T, *Q2, *K2, *VT2, *S;
    cudaGetSymbolAddress((void**)&Q1,  g_Q1);
    cudaGetSymbolAddress((void**)&K1,  g_K1);
    cudaGetSymbolAddress((void**)&VT1, g_VT1);
    cudaGetSymbolAddress((void**)&O1,  g_O1);
    cudaGetSymbolAddress((void**)&T,   g_T);
    cudaGetSymbolAddress((void**)&Q2,  g_Q2);
    cudaGetSymbolAddress((void**)&K2,  g_K2);
    cudaGetSymbolAddress((void**)&VT2, g_VT2);
    cudaGetSymbolAddress((void**)&S,   g_S);

    cudaFuncSetAttribute(gemm_tc, cudaFuncAttributeMaxDynamicSharedMemorySize,
                         SMEM_BYTES);

    const dim3 blk(256);
    const long long HALF = 8192LL * 512;

    // --- Stage 1: QKV projections (x and y; shared sa1 weights) ------------
    dim3 g1(512 / 128, 8192 / 128);
    gemm_tc<<<g1, blk, SMEM_BYTES>>>(x, Wq1, bq1, Q1,        8192, 512, 512, 0, 0, 0, 0, 0);
    gemm_tc<<<g1, blk, SMEM_BYTES>>>(y, Wq1, bq1, Q1 + HALF, 8192, 512, 512, 0, 0, 0, 0, 0);
    gemm_tc<<<g1, blk, SMEM_BYTES>>>(x, Wk1, bk1, K1,        8192, 512, 512, 0, 0, 0, 0, 0);
    gemm_tc<<<g1, blk, SMEM_BYTES>>>(y, Wk1, bk1, K1 + HALF, 8192, 512, 512, 0, 0, 0, 0, 0);
    gemm_tc<<<g1, blk, SMEM_BYTES>>>(x, Wv1, bv1, VT1,                    8192, 512, 512, 0, 0, 0, 1, 512);
    gemm_tc<<<g1, blk, SMEM_BYTES>>>(y, Wv1, bv1, VT1 + 4LL * 512 * 2048, 8192, 512, 512, 0, 0, 0, 1, 512);

    // --- Stage 1: scores = Q K^T (8 batches), softmax, P V -----------------
    dim3 gs1(2048 / 128, 2048 / 128, 8);
    gemm_tc<<<gs1, blk, SMEM_BYTES>>>(Q1, K1, nullptr, S, 2048, 2048, 512,
                                      2048LL * 512, 2048LL * 512, 2048LL * 2048, 0, 0);
    softmax2048<<<16384, 256>>>(S);
    dim3 gp1(512 / 128, 2048 / 128, 8);
    gemm_tc<<<gp1, blk, SMEM_BYTES>>>(S, VT1, nullptr, O1, 2048, 512, 2048,
                                      2048LL * 2048, 512LL * 2048, 2048LL * 512, 0, 0);

    // --- temp = concat(x1 + y*w2, y1 + x*w1) -------------------------------
    build_temp<<<(8192 * 1024) / 256, 256>>>(O1, x, y, w1, w2, T);

    // --- Stage 2: QKV projections ------------------------------------------
    dim3 g2(1024 / 128, 8192 / 128);
    gemm_tc<<<g2, blk, SMEM_BYTES>>>(T, Wq2, bq2, Q2, 8192, 1024, 1024, 0, 0, 0, 0, 0);
    gemm_tc<<<g2, blk, SMEM_BYTES>>>(T, Wk2, bk2, K2, 8192, 1024, 1024, 0, 0, 0, 0, 0);
    gemm_tc<<<g2, blk, SMEM_BYTES>>>(T, Wv2, bv2, VT2, 8192, 1024, 1024, 0, 0, 0, 1, 1024);

    // --- Stage 2: scores (4 batches), softmax, P V -> out ------------------
    dim3 gs2(2048 / 128, 2048 / 128, 4);
    gemm_tc<<<gs2, blk, SMEM_BYTES>>>(Q2, K2, nullptr, S, 2048, 2048, 1024,
                                      2048LL * 1024, 2048LL * 1024, 2048LL * 2048, 0, 0);
    softmax2048<<<8192, 256>>>(S);
    dim3 gp2(1024 / 128, 2048 / 128, 4);
    gemm_tc<<<gp2, blk, SMEM_BYTES>>>(S, VT2, nullptr, out, 2048, 1024, 2048,
                                      2048LL * 2048, 1024LL * 2048, 2048LL * 1024, 0, 0);
}

// round 4
// speedup vs baseline: 2.4881x; 1.3487x over previous
#include <cuda_runtime.h>
#include <cuda_bf16.h>
#include <cstdint>

// ===========================================================================
// Cross-attention. All GEMMs: bf16 split-precision x3 HMMA (fp32 acc),
// cp.async 4-stage pipeline, 128x128 block tile, 8 warps (warp 64x32).
// Operands pre-split once into bf16 hi/lo planes; GEMM epilogues write
// split planes directly for intermediates consumed by later GEMMs.
// ===========================================================================

// ---------------- helpers ----------------
__device__ __forceinline__ uint32_t smem_u32(const void* p) {
    uint32_t a;
    asm("{ .reg .u64 t; cvta.to.shared.u64 t, %1; cvt.u32.u64 %0, t; }"
        : "=r"(a) : "l"(p));
    return a;
}
__device__ __forceinline__ void ldsm_x4(uint32_t* r, uint32_t addr) {
    asm volatile("ldmatrix.sync.aligned.m8n8.x4.shared.b16 {%0,%1,%2,%3}, [%4];"
                 : "=r"(r[0]), "=r"(r[1]), "=r"(r[2]), "=r"(r[3]) : "r"(addr));
}
__device__ __forceinline__ void mma16816(float* d, const uint32_t* a,
                                         uint32_t b0, uint32_t b1) {
    asm volatile(
        "mma.sync.aligned.m16n8k16.row.col.f32.bf16.bf16.f32 "
        "{%0,%1,%2,%3}, {%4,%5,%6,%7}, {%8,%9}, {%0,%1,%2,%3};"
        : "+f"(d[0]), "+f"(d[1]), "+f"(d[2]), "+f"(d[3])
        : "r"(a[0]), "r"(a[1]), "r"(a[2]), "r"(a[3]), "r"(b0), "r"(b1));
}
__device__ __forceinline__ void cp16(uint32_t s, const void* g) {
    asm volatile("cp.async.cg.shared.global [%0], [%1], 16;" :: "r"(s), "l"(g));
}

// ---------------- scratch (static device memory; bf16 hi/lo planes) -------
__device__ __nv_bfloat16 g_xyh[16384LL * 512], g_xyl[16384LL * 512];
__device__ __nv_bfloat16 g_wq1h[512 * 512],  g_wq1l[512 * 512];
__device__ __nv_bfloat16 g_wk1h[512 * 512],  g_wk1l[512 * 512];
__device__ __nv_bfloat16 g_wv1h[512 * 512],  g_wv1l[512 * 512];
__device__ __nv_bfloat16 g_wq2h[1024 * 1024], g_wq2l[1024 * 1024];
__device__ __nv_bfloat16 g_wk2h[1024 * 1024], g_wk2l[1024 * 1024];
__device__ __nv_bfloat16 g_wv2h[1024 * 1024], g_wv2l[1024 * 1024];
__device__ __nv_bfloat16 g_Q1h[16384LL * 512], g_Q1l[16384LL * 512];
__device__ __nv_bfloat16 g_K1h[16384LL * 512], g_K1l[16384LL * 512];
__device__ __nv_bfloat16 g_VT1h[16384LL * 512], g_VT1l[16384LL * 512];  // [8][512][2048]
__device__ float         g_S [8LL * 2048 * 2048];
__device__ __nv_bfloat16 g_Ph[8LL * 2048 * 2048], g_Pl[8LL * 2048 * 2048];
__device__ float         g_O1[16384LL * 512];
__device__ __nv_bfloat16 g_Th[8192LL * 1024], g_Tl[8192LL * 1024];
__device__ __nv_bfloat16 g_Q2h[8192LL * 1024], g_Q2l[8192LL * 1024];
__device__ __nv_bfloat16 g_K2h[8192LL * 1024], g_K2l[8192LL * 1024];
__device__ __nv_bfloat16 g_VT2h[8192LL * 1024], g_VT2l[8192LL * 1024]; // [4][1024][2048]

// SMEM: 4 stages x 32KB. Stage: Ah +0, Al +8192, Bh +16384, Bl +24576.
static constexpr int SMEM_BYTES = 131072;

// ===========================================================================
// NT GEMM: C[M,N] = (Ah+Al)[M,K] * (Bh+Bl)[N,K]^T (+bias), 3-pass bf16 HMMA.
//   mode 0: Cf fp32 [row*N+col]
//   mode 1: Ch/Cl split bf16 [row*N+col]
//   mode 2: Ch/Cl split bf16 transposed VT layout:
//           idx = (row>>11)*ntot*2048 + col*2048 + (row&2047)
// Requires M%128==0, N%128==0, K%128==0 (nch>=4); ldA=ldB=K.
// ===========================================================================
__global__ void __launch_bounds__(256, 1)
gemm_bf3(const __nv_bfloat16* __restrict__ Ah, const __nv_bfloat16* __restrict__ Al,
         const __nv_bfloat16* __restrict__ Bh, const __nv_bfloat16* __restrict__ Bl,
         const float* __restrict__ bias,
         float* __restrict__ Cf,
         __nv_bfloat16* __restrict__ Ch, __nv_bfloat16* __restrict__ Cl,
         int M, int N, int K,
         long long sA, long long sB, long long sC,
         int mode, int ntot)
{
    extern __shared__ char smem[];
    const uint32_t sb = smem_u32(smem);
    const int tid = threadIdx.x;
    const int lane = tid & 31;
    const int wid = tid >> 5;
    const int z = blockIdx.z;

    Ah += (long long)z * sA;  Al += (long long)z * sA;
    Bh += (long long)z * sB;  Bl += (long long)z * sB;
    if (Cf) Cf += (long long)z * sC;
    if (Ch) { Ch += (long long)z * sC; Cl += (long long)z * sC; }

    const int m0 = blockIdx.y * 128;
    const int n0 = blockIdx.x * 128;
    const int m0w = (wid & 1) * 64;
    const int n0w = (wid >> 1) * 32;

    // per-thread cp.async coords: 2 iters x 4 planes, 16B each
    const int r0 = tid >> 2, c0 = tid & 3;
    const uint32_t soff0 = (uint32_t)r0 * 64 + (uint32_t)((c0 ^ ((r0 >> 1) & 3)) << 4);
    const __nv_bfloat16* gAh0 = Ah + (long long)(m0 + r0) * K + c0 * 8;
    const __nv_bfloat16* gAl0 = Al + (long long)(m0 + r0) * K + c0 * 8;
    const __nv_bfloat16* gBh0 = Bh + (long long)(n0 + r0) * K + c0 * 8;
    const __nv_bfloat16* gBl0 = Bl + (long long)(n0 + r0) * K + c0 * 8;
    const long long rstep = 64LL * K;

#define ISSUE(chv) do {                                                         \
    const long long k0_ = (long long)(chv) * 32;                                \
    const uint32_t sba_ = sb + (uint32_t)((chv) & 3) * 32768u;                  \
    cp16(sba_ + soff0,                 gAh0 + k0_);                             \
    cp16(sba_ + soff0 + 4096,          gAh0 + rstep + k0_);                     \
    cp16(sba_ + 8192 + soff0,          gAl0 + k0_);                             \
    cp16(sba_ + 8192 + soff0 + 4096,   gAl0 + rstep + k0_);                     \
    cp16(sba_ + 16384 + soff0,         gBh0 + k0_);                             \
    cp16(sba_ + 16384 + soff0 + 4096,  gBh0 + rstep + k0_);                     \
    cp16(sba_ + 24576 + soff0,         gBl0 + k0_);                             \
    cp16(sba_ + 24576 + soff0 + 4096,  gBl0 + rstep + k0_);                     \
    asm volatile("cp.async.commit_group;" ::: "memory");                        \
} while (0)

    float acc[4][4][4];
#pragma unroll
    for (int i = 0; i < 4; i++)
#pragma unroll
        for (int j = 0; j < 4; j++)
#pragma unroll
            for (int k = 0; k < 4; k++) acc[i][j][k] = 0.f;

    const int nch = K >> 5;
    ISSUE(0); ISSUE(1); ISSUE(2);

    const int arow = m0w + (lane & 15);
    const int brow = n0w + (lane & 15);

    for (int ch = 0; ch < nch; ch++) {
        asm volatile("cp.async.wait_group 2;" ::: "memory");
        __syncthreads();
        if (ch + 3 < nch) ISSUE(ch + 3);

        const uint32_t stb = sb + (uint32_t)(ch & 3) * 32768u;
#pragma unroll
        for (int kstep = 0; kstep < 2; kstep++) {
            const int kc = kstep * 2 + (lane >> 4);
            uint32_t aH[4][4], aL[4][4], bh[2][4], bl[2][4];
#pragma unroll
            for (int mf = 0; mf < 4; mf++) {
                const int rr = arow + mf * 16;
                const uint32_t off =
                    (uint32_t)rr * 64 + (uint32_t)((kc ^ ((rr >> 1) & 3)) << 4);
                ldsm_x4(aH[mf], stb + off);
                ldsm_x4(aL[mf], stb + 8192 + off);
            }
#pragma unroll
            for (int q = 0; q < 2; q++) {
                const int rr = brow + q * 16;
                const uint32_t off =
                    (uint32_t)rr * 64 + (uint32_t)((kc ^ ((rr >> 1) & 3)) << 4);
                ldsm_x4(bh[q], stb + 16384 + off);
                ldsm_x4(bl[q], stb + 24576 + off);
            }
#pragma unroll
            for (int mf = 0; mf < 4; mf++)
#pragma unroll
                for (int nf = 0; nf < 4; nf++) {
                    const uint32_t b0h = bh[nf >> 1][nf & 1];
                    const uint32_t b1h = bh[nf >> 1][(nf & 1) + 2];
                    const uint32_t b0l = bl[nf >> 1][nf & 1];
                    const uint32_t b1l = bl[nf >> 1][(nf & 1) + 2];
                    mma16816(acc[mf][nf], aH[mf], b0h, b1h);
                    mma16816(acc[mf][nf], aH[mf], b0l, b1l);
                    mma16816(acc[mf][nf], aL[mf], b0h, b1h);
                }
        }
        __syncthreads();
    }
#undef ISSUE

    // ---- epilogue ----
    const int gr = lane >> 2;
    const int gc = (lane & 3) * 2;

    if (mode == 0) {
#pragma unroll
        for (int mf = 0; mf < 4; mf++)
#pragma unroll
            for (int nf = 0; nf < 4; nf++) {
                const int row = m0 + m0w + mf * 16 + gr;
                const int col = n0 + n0w + nf * 8 + gc;
                float b0 = 0.f, b1 = 0.f;
                if (bias) { b0 = bias[col]; b1 = bias[col + 1]; }
                float2 v0 = make_float2(acc[mf][nf][0] + b0, acc[mf][nf][1] + b1);
                float2 v1 = make_float2(acc[mf][nf][2] + b0, acc[mf][nf][3] + b1);
                *reinterpret_cast<float2*>(Cf + (long long)row * N + col) = v0;
                *reinterpret_cast<float2*>(Cf + (long long)(row + 8) * N + col) = v1;
            }
    } else if (mode == 1) {
#pragma unroll
        for (int mf = 0; mf < 4; mf++)
#pragma unroll
            for (int nf = 0; nf < 4; nf++) {
                const int row = m0 + m0w + mf * 16 + gr;
                const int col = n0 + n0w + nf * 8 + gc;
                float b0 = 0.f, b1 = 0.f;
                if (bias) { b0 = bias[col]; b1 = bias[col + 1]; }
#pragma unroll
                for (int half = 0; half < 2; half++) {
                    const float v0 = acc[mf][nf][half * 2 + 0] + b0;
                    const float v1 = acc[mf][nf][half * 2 + 1] + b1;
                    __nv_bfloat16 h0 = __float2bfloat16(v0);
                    __nv_bfloat16 h1 = __float2bfloat16(v1);
                    __nv_bfloat162 hh; hh.x = h0; hh.y = h1;
                    __nv_bfloat162 ll;
                    ll.x = __float2bfloat16(v0 - __bfloat162float(h0));
                    ll.y = __float2bfloat16(v1 - __bfloat162float(h1));
                    const long long idx = (long long)(row + half * 8) * N + col;
                    *reinterpret_cast<__nv_bfloat162*>(Ch + idx) = hh;
                    *reinterpret_cast<__nv_bfloat162*>(Cl + idx) = ll;
                }
            }
    } else {
        // transposed split epilogue: stage fp32 per warp in smem
        __syncthreads();
        float* tw = reinterpret_cast<float*>(smem) + wid * 2080;
#pragma unroll
        for (int mf = 0; mf < 4; mf++)
#pragma unroll
            for (int nf = 0; nf < 4; nf++) {
                const int rl = mf * 16 + gr;
                const int cl = nf * 8 + gc;
                tw[cl * 65 + rl]           = acc[mf][nf][0];
                tw[(cl + 1) * 65 + rl]     = acc[mf][nf][1];
                tw[cl * 65 + rl + 8]       = acc[mf][nf][2];
                tw[(cl + 1) * 65 + rl + 8] = acc[mf][nf][3];
            }
        __syncwarp();
        const int g0 = m0 + m0w;
        const long long basev = (long long)(g0 >> 11) * ntot * 2048 + (g0 & 2047);
#pragma unroll 4
        for (int c = 0; c < 32; c++) {
            const int colg = n0 + n0w + c;
            const float bb = bias ? bias[colg] : 0.f;
            const float v0 = tw[c * 65 + lane * 2] + bb;
            const float v1 = tw[c * 65 + lane * 2 + 1] + bb;
            __nv_bfloat16 h0 = __float2bfloat16(v0);
            __nv_bfloat16 h1 = __float2bfloat16(v1);
            __nv_bfloat162 hh; hh.x = h0; hh.y = h1;
            __nv_bfloat162 ll;
            ll.x = __float2bfloat16(v0 - __bfloat162float(h0));
            ll.y = __float2bfloat16(v1 - __bfloat162float(h1));
            const long long idx = basev + (long long)colg * 2048 + lane * 2;
            *reinterpret_cast<__nv_bfloat162*>(Ch + idx) = hh;
            *reinterpret_cast<__nv_bfloat162*>(Cl + idx) = ll;
        }
    }
}

// ---------------------------------------------------------------------------
// split fp32 -> bf16 hi/lo planes (vectorized by 2)
// ---------------------------------------------------------------------------
__global__ void __launch_bounds__(256)
split_f32(const float* __restrict__ src, __nv_bfloat16* __restrict__ h,
          __nv_bfloat16* __restrict__ l, long long n2)
{
    long long i = (long long)blockIdx.x * 256 + threadIdx.x;
    if (i >= n2) return;
    float2 v = reinterpret_cast<const float2*>(src)[i];
    __nv_bfloat16 h0 = __float2bfloat16(v.x);
    __nv_bfloat16 h1 = __float2bfloat16(v.y);
    __nv_bfloat162 hh; hh.x = h0; hh.y = h1;
    __nv_bfloat162 ll;
    ll.x = __float2bfloat16(v.x - __bfloat162float(h0));
    ll.y = __float2bfloat16(v.y - __bfloat162float(h1));
    reinterpret_cast<__nv_bfloat162*>(h)[i] = hh;
    reinterpret_cast<__nv_bfloat162*>(l)[i] = ll;
}

// ---------------------------------------------------------------------------
// Row softmax over 2048 cols; fp32 in, split bf16 hi/lo out. Block = row.
// ---------------------------------------------------------------------------
__global__ void __launch_bounds__(256)
softmax2048(const float* __restrict__ S, __nv_bfloat16* __restrict__ Ph,
            __nv_bfloat16* __restrict__ Pl)
{
    const float* p = S + (long long)blockIdx.x * 2048;
    const int t = threadIdx.x;

    float v[8];
    {
        const float4* p4 = reinterpret_cast<const float4*>(p + t * 8);
        float4 a = p4[0], b = p4[1];
        v[0] = a.x; v[1] = a.y; v[2] = a.z; v[3] = a.w;
        v[4] = b.x; v[5] = b.y; v[6] = b.z; v[7] = b.w;
    }

    float m = v[0];
#pragma unroll
    for (int i = 1; i < 8; i++) m = fmaxf(m, v[i]);

    __shared__ float red[8];
#pragma unroll
    for (int o = 16; o > 0; o >>= 1) m = fmaxf(m, __shfl_xor_sync(0xffffffffu, m, o));
    if ((t & 31) == 0) red[t >> 5] = m;
    __syncthreads();
    if (t < 32) {
        float mm = (t < 8) ? red[t] : -3.4e38f;
#pragma unroll
        for (int o = 4; o > 0; o >>= 1) mm = fmaxf(mm, __shfl_xor_sync(0xffffffffu, mm, o));
        if (t == 0) red[0] = mm;
    }
    __syncthreads();
    m = red[0];
    __syncthreads();

    float s = 0.f;
#pragma unroll
    for (int i = 0; i < 8; i++) { v[i] = __expf(v[i] - m); s += v[i]; }
#pragma unroll
    for (int o = 16; o > 0; o >>= 1) s += __shfl_xor_sync(0xffffffffu, s, o);
    if ((t & 31) == 0) red[t >> 5] = s;
    __syncthreads();
    if (t < 32) {
        float ss = (t < 8) ? red[t] : 0.f;
#pragma unroll
        for (int o = 4; o > 0; o >>= 1) ss += __shfl_xor_sync(0xffffffffu, ss, o);
        if (t == 0) red[0] = ss;
    }
    __syncthreads();
    const float inv = 1.f / red[0];

    __nv_bfloat162* oh =
        reinterpret_cast<__nv_bfloat162*>(Ph + (long long)blockIdx.x * 2048 + t * 8);
    __nv_bfloat162* ol =
        reinterpret_cast<__nv_bfloat162*>(Pl + (long long)blockIdx.x * 2048 + t * 8);
#pragma unroll
    for (int i = 0; i < 4; i++) {
        const float v0 = v[i * 2] * inv;
        const float v1 = v[i * 2 + 1] * inv;
        __nv_bfloat16 h0 = __float2bfloat16(v0);
        __nv_bfloat16 h1 = __float2bfloat16(v1);
        __nv_bfloat162 hh; hh.x = h0; hh.y = h1;
        __nv_bfloat162 ll;
        ll.x = __float2bfloat16(v0 - __bfloat162float(h0));
        ll.y = __float2bfloat16(v1 - __bfloat162float(h1));
        oh[i] = hh;
        ol[i] = ll;
    }
}

// ---------------------------------------------------------------------------
// temp = concat(x1 + y*w2, y1 + x*w1), written as split bf16 planes.
// ---------------------------------------------------------------------------
__global__ void __launch_bounds__(256)
build_temp(const float* __restrict__ O1,
           const float* __restrict__ x, const float* __restrict__ y,
           const float* __restrict__ w1, const float* __restrict__ w2,
           __nv_bfloat16* __restrict__ Th, __nv_bfloat16* __restrict__ Tl)
{
    long long i2 = (long long)blockIdx.x * 256 + threadIdx.x;  // pair index
    if (i2 >= 8192LL * 512) return;
    const int colp = (int)(i2 & 511);       // pair column 0..511
    const long long tok = i2 >> 9;
    const int col = colp * 2;
    float2 v;
    if (col < 512) {
        float2 o = *reinterpret_cast<const float2*>(O1 + tok * 512 + col);
        float2 yy = *reinterpret_cast<const float2*>(y + tok * 512 + col);
        v.x = o.x + yy.x * w2[0];
        v.y = o.y + yy.y * w2[0];
    } else {
        const int c = col - 512;
        float2 o = *reinterpret_cast<const float2*>(O1 + (8192 + tok) * 512 + c);
        float2 xx = *reinterpret_cast<const float2*>(x + tok * 512 + c);
        v.x = o.x + xx.x * w1[0];
        v.y = o.y + xx.y * w1[0];
    }
    __nv_bfloat16 h0 = __float2bfloat16(v.x);
    __nv_bfloat16 h1 = __float2bfloat16(v.y);
    __nv_bfloat162 hh; hh.x = h0; hh.y = h1;
    __nv_bfloat162 ll;
    ll.x = __float2bfloat16(v.x - __bfloat162float(h0));
    ll.y = __float2bfloat16(v.y - __bfloat162float(h1));
    reinterpret_cast<__nv_bfloat162*>(Th)[i2] = hh;
    reinterpret_cast<__nv_bfloat162*>(Tl)[i2] = ll;
}

// ---------------------------------------------------------------------------
extern "C" void kernel_launch(void* const* d_in, const int* in_sizes, int n_in,
                              void* d_out, int out_size)
{
    (void)in_sizes; (void)n_in; (void)out_size;

    const float* x   = (const float*)d_in[0];
    const float* y   = (const float*)d_in[1];
    const float* Wq1 = (const float*)d_in[2];
    const float* bq1 = (const float*)d_in[3];
    const float* Wk1 = (const float*)d_in[4];
    const float* bk1 = (const float*)d_in[5];
    const float* Wv1 = (const float*)d_in[6];
    const float* bv1 = (const float*)d_in[7];
    const float* Wq2 = (const float*)d_in[8];
    const float* bq2 = (const float*)d_in[9];
    const float* Wk2 = (const float*)d_in[10];
    const float* bk2 = (const float*)d_in[11];
    const float* Wv2 = (const float*)d_in[12];
    const float* bv2 = (const float*)d_in[13];
    const float* w1  = (const float*)d_in[14];
    const float* w2  = (const float*)d_in[15];
    float* out = (float*)d_out;

    __nv_bfloat16 *xyh, *xyl, *wq1h, *wq1l, *wk1h, *wk1l, *wv1h, *wv1l;
    __nv_bfloat16 *wq2h, *wq2l, *wk2h, *wk2l, *wv2h, *wv2l;
    __nv_bfloat16 *Q1h, *Q1l, *K1h, *K1l, *VT1h, *VT1l, *Ph, *Pl;
    __nv_bfloat16 *Th, *Tl, *Q2h, *Q2l, *K2h, *K2l, *VT2h, *VT2l;
    float *S, *O1;
    cudaGetSymbolAddress((void**)&xyh, g_xyh);   cudaGetSymbolAddress((void**)&xyl, g_xyl);
    cudaGetSymbolAddress((void**)&wq1h, g_wq1h); cudaGetSymbolAddress((void**)&wq1l, g_wq1l);
    cudaGetSymbolAddress((void**)&wk1h, g_wk1h); cudaGetSymbolAddress((void**)&wk1l, g_wk1l);
    cudaGetSymbolAddress((void**)&wv1h, g_wv1h); cudaGetSymbolAddress((void**)&wv1l, g_wv1l);
    cudaGetSymbolAddress((void**)&wq2h, g_wq2h); cudaGetSymbolAddress((void**)&wq2l, g_wq2l);
    cudaGetSymbolAddress((void**)&wk2h, g_wk2h); cudaGetSymbolAddress((void**)&wk2l, g_wk2l);
    cudaGetSymbolAddress((void**)&wv2h, g_wv2h); cudaGetSymbolAddress((void**)&wv2l, g_wv2l);
    cudaGetSymbolAddress((void**)&Q1h, g_Q1h);   cudaGetSymbolAddress((void**)&Q1l, g_Q1l);
    cudaGetSymbolAddress((void**)&K1h, g_K1h);   cudaGetSymbolAddress((void**)&K1l, g_K1l);
    cudaGetSymbolAddress((void**)&VT1h, g_VT1h); cudaGetSymbolAddress((void**)&VT1l, g_VT1l);
    cudaGetSymbolAddress((void**)&S, g_S);
    cudaGetSymbolAddress((void**)&Ph, g_Ph);     cudaGetSymbolAddress((void**)&Pl, g_Pl);
    cudaGetSymbolAddress((void**)&O1, g_O1);
    cudaGetSymbolAddress((void**)&Th, g_Th);     cudaGetSymbolAddress((void**)&Tl, g_Tl);
    cudaGetSymbolAddress((void**)&Q2h, g_Q2h);   cudaGetSymbolAddress((void**)&Q2l, g_Q2l);
    cudaGetSymbolAddress((void**)&K2h, g_K2h);   cudaGetSymbolAddress((void**)&K2l, g_K2l);
    cudaGetSymbolAddress((void**)&VT2h, g_VT2h); cudaGetSymbolAddress((void**)&VT2l, g_VT2l);

    cudaFuncSetAttribute(gemm_bf3, cudaFuncAttributeMaxDynamicSharedMemorySize,
                         SMEM_BYTES);

    const dim3 blk(256);
    const long long HX = 8192LL * 512;

    // --- pre-split inputs and weights --------------------------------------
    split_f32<<<(int)((HX / 2 + 255) / 256), blk>>>(x, xyh, xyl, HX / 2);
    split_f32<<<(int)((HX / 2 + 255) / 256), blk>>>(y, xyh + HX, xyl + HX, HX / 2);
    split_f32<<<512, blk>>>(Wq1, wq1h, wq1l, 512 * 512 / 2);
    split_f32<<<512, blk>>>(Wk1, wk1h, wk1l, 512 * 512 / 2);
    split_f32<<<512, blk>>>(Wv1, wv1h, wv1l, 512 * 512 / 2);
    split_f32<<<2048, blk>>>(Wq2, wq2h, wq2l, 1024 * 1024 / 2);
    split_f32<<<2048, blk>>>(Wk2, wk2h, wk2l, 1024 * 1024 / 2);
    split_f32<<<2048, blk>>>(Wv2, wv2h, wv2l, 1024 * 1024 / 2);

    // --- Stage 1: QKV projections (x,y stacked: M=16384) -------------------
    dim3 g1(512 / 128, 16384 / 128);
    gemm_bf3<<<g1, blk, SMEM_BYTES>>>(xyh, xyl, wq1h, wq1l, bq1,
                                      nullptr, Q1h, Q1l, 16384, 512, 512, 0, 0, 0, 1, 0);
    gemm_bf3<<<g1, blk, SMEM_BYTES>>>(xyh, xyl, wk1h, wk1l, bk1,
                                      nullptr, K1h, K1l, 16384, 512, 512, 0, 0, 0, 1, 0);
    gemm_bf3<<<g1, blk, SMEM_BYTES>>>(xyh, xyl, wv1h, wv1l, bv1,
                                      nullptr, VT1h, VT1l, 16384, 512, 512, 0, 0, 0, 2, 512);

    // --- Stage 1: scores (8 batches), softmax, P V -------------------------
    dim3 gs1(2048 / 128, 2048 / 128, 8);
    gemm_bf3<<<gs1, blk, SMEM_BYTES>>>(Q1h, Q1l, K1h, K1l, nullptr,
                                       S, nullptr, nullptr, 2048, 2048, 512,
                                       2048LL * 512, 2048LL * 512, 2048LL * 2048, 0, 0);
    softmax2048<<<16384, blk>>>(S, Ph, Pl);
    dim3 gp1(512 / 128, 2048 / 128, 8);
    gemm_bf3<<<gp1, blk, SMEM_BYTES>>>(Ph, Pl, VT1h, VT1l, nullptr,
                                       O1, nullptr, nullptr, 2048, 512, 2048,
                                       2048LL * 2048, 512LL * 2048, 2048LL * 512, 0, 0);

    // --- temp = concat(x1 + y*w2, y1 + x*w1), split ------------------------
    build_temp<<<(int)((8192LL * 512 + 255) / 256), blk>>>(O1, x, y, w1, w2, Th, Tl);

    // --- Stage 2: QKV projections ------------------------------------------
    dim3 g2(1024 / 128, 8192 / 128);
    gemm_bf3<<<g2, blk, SMEM_BYTES>>>(Th, Tl, wq2h, wq2l, bq2,
                                      nullptr, Q2h, Q2l, 8192, 1024, 1024, 0, 0, 0, 1, 0);
    gemm_bf3<<<g2, blk, SMEM_BYTES>>>(Th, Tl, wk2h, wk2l, bk2,
                                      nullptr, K2h, K2l, 8192, 1024, 1024, 0, 0, 0, 1, 0);
    gemm_bf3<<<g2, blk, SMEM_BYTES>>>(Th, Tl, wv2h, wv2l, bv2,
                                      nullptr, VT2h, VT2l, 8192, 1024, 1024, 0, 0, 0, 2, 1024);

    // --- Stage 2: scores (4 batches), softmax, P V -> out ------------------
    dim3 gs2(2048 / 128, 2048 / 128, 4);
    gemm_bf3<<<gs2, blk, SMEM_BYTES>>>(Q2h, Q2l, K2h, K2l, nullptr,
                                       S, nullptr, nullptr, 2048, 2048, 1024,
                                       2048LL * 1024, 2048LL * 1024, 2048LL * 2048, 0, 0);
    softmax2048<<<8192, blk>>>(S, Ph, Pl);
    dim3 gp2(1024 / 128, 2048 / 128, 4);
    gemm_bf3<<<gp2, blk, SMEM_BYTES>>>(Ph, Pl, VT2h, VT2l, nullptr,
                                       out, nullptr, nullptr, 2048, 1024, 2048,
                                       2048LL * 2048, 1024LL * 2048, 2048LL * 1024, 0, 0);
}

// round 5
// speedup vs baseline: 2.7005x; 1.0854x over previous
#include <cuda_runtime.h>
#include <cuda_bf16.h>
#include <cstdint>

// ===========================================================================
// Cross-attention. All GEMMs: bf16 split-precision x3 HMMA (fp32 acc),
// cp.async 4-stage pipeline (single sync/chunk), 128x128 tile, 8 warps.
// QKV fused per stage via concatenated weight planes + routing epilogue.
// build_temp fused into PV1 epilogue.
// ===========================================================================

// ---------------- helpers ----------------
__device__ __forceinline__ uint32_t smem_u32(const void* p) {
    uint32_t a;
    asm("{ .reg .u64 t; cvta.to.shared.u64 t, %1; cvt.u32.u64 %0, t; }"
        : "=r"(a) : "l"(p));
    return a;
}
__device__ __forceinline__ void ldsm_x4(uint32_t* r, uint32_t addr) {
    asm volatile("ldmatrix.sync.aligned.m8n8.x4.shared.b16 {%0,%1,%2,%3}, [%4];"
                 : "=r"(r[0]), "=r"(r[1]), "=r"(r[2]), "=r"(r[3]) : "r"(addr));
}
__device__ __forceinline__ void mma16816(float* d, const uint32_t* a,
                                         uint32_t b0, uint32_t b1) {
    asm volatile(
        "mma.sync.aligned.m16n8k16.row.col.f32.bf16.bf16.f32 "
        "{%0,%1,%2,%3}, {%4,%5,%6,%7}, {%8,%9}, {%0,%1,%2,%3};"
        : "+f"(d[0]), "+f"(d[1]), "+f"(d[2]), "+f"(d[3])
        : "r"(a[0]), "r"(a[1]), "r"(a[2]), "r"(a[3]), "r"(b0), "r"(b1));
}
__device__ __forceinline__ void cp16(uint32_t s, const void* g) {
    asm volatile("cp.async.cg.shared.global [%0], [%1], 16;" :: "r"(s), "l"(g));
}
__device__ __forceinline__ void split2(float v0, float v1,
                                       __nv_bfloat162& hh, __nv_bfloat162& ll) {
    __nv_bfloat16 h0 = __float2bfloat16(v0);
    __nv_bfloat16 h1 = __float2bfloat16(v1);
    hh.x = h0; hh.y = h1;
    ll.x = __float2bfloat16(v0 - __bfloat162float(h0));
    ll.y = __float2bfloat16(v1 - __bfloat162float(h1));
}

// ---------------- scratch (static device memory; bf16 hi/lo planes) -------
__device__ __nv_bfloat16 g_xyh[16384LL * 512], g_xyl[16384LL * 512];
__device__ __nv_bfloat16 g_w1h[1536 * 512],   g_w1l[1536 * 512];    // [q;k;v]
__device__ __nv_bfloat16 g_w2h[3072 * 1024],  g_w2l[3072 * 1024];   // [q;k;v]
__device__ float         g_b1[1536], g_b2[3072];
__device__ __nv_bfloat16 g_Q1h[16384LL * 512], g_Q1l[16384LL * 512];
__device__ __nv_bfloat16 g_K1h[16384LL * 512], g_K1l[16384LL * 512];
__device__ __nv_bfloat16 g_VT1h[16384LL * 512], g_VT1l[16384LL * 512]; // [8][512][2048]
__device__ float         g_S [8LL * 2048 * 2048];
__device__ __nv_bfloat16 g_Ph[8LL * 2048 * 2048], g_Pl[8LL * 2048 * 2048];
__device__ __nv_bfloat16 g_Th[8192LL * 1024], g_Tl[8192LL * 1024];
__device__ __nv_bfloat16 g_Q2h[8192LL * 1024], g_Q2l[8192LL * 1024];
__device__ __nv_bfloat16 g_K2h[8192LL * 1024], g_K2l[8192LL * 1024];
__device__ __nv_bfloat16 g_VT2h[8192LL * 1024], g_VT2l[8192LL * 1024]; // [4][1024][2048]

// SMEM: 4 stages x 32KB. Stage: Ah +0, Al +8192, Bh +16384, Bl +24576.
static constexpr int SMEM_BYTES = 131072;

// ===========================================================================
// NT GEMM: C[M,N] = (Ah+Al)[M,K]*(Bh+Bl)[N,K]^T, 3-pass bf16 HMMA, fp32 acc.
// Epilogue modes:
//   0: Cf fp32 [row*N+col], batched by z*sC  (bias optional)
//   3: QKV routing over concat N: seg=col/segN -> 0:P0 split planes,
//      1:P1 split planes, 2:P2 transposed VT split planes (batch=row>>11)
//   4: PV1+build_temp: T planes; grow=z*2048+row; grow<8192: tcol=col,
//      resid=ry*w2; else tok=grow-8192, tcol=col+512, resid=rx*w1.
// Requires M%128==0, N%128==0, K%128==0.
// ===========================================================================
__global__ void __launch_bounds__(256, 1)
gemm_bf3(const __nv_bfloat16* __restrict__ Ah, const __nv_bfloat16* __restrict__ Al,
         const __nv_bfloat16* __restrict__ Bh, const __nv_bfloat16* __restrict__ Bl,
         const float* __restrict__ bias,
         float* __restrict__ Cf,
         __nv_bfloat16* __restrict__ P0h, __nv_bfloat16* __restrict__ P0l,
         __nv_bfloat16* __restrict__ P1h, __nv_bfloat16* __restrict__ P1l,
         __nv_bfloat16* __restrict__ P2h, __nv_bfloat16* __restrict__ P2l,
         const float* __restrict__ rx, const float* __restrict__ ry,
         const float* __restrict__ rw1, const float* __restrict__ rw2,
         int M, int N, int K,
         long long sA, long long sB, long long sC,
         int mode, int segN)
{
    extern __shared__ char smem[];
    const uint32_t sb = smem_u32(smem);
    const int tid = threadIdx.x;
    const int lane = tid & 31;
    const int wid = tid >> 5;
    const int z = blockIdx.z;

    Ah += (long long)z * sA;  Al += (long long)z * sA;
    Bh += (long long)z * sB;  Bl += (long long)z * sB;
    if (Cf) Cf += (long long)z * sC;

    const int m0 = blockIdx.y * 128;
    const int n0 = blockIdx.x * 128;
    const int m0w = (wid & 1) * 64;
    const int n0w = (wid >> 1) * 32;

    const int r0 = tid >> 2, c0 = tid & 3;
    const uint32_t soff0 = (uint32_t)r0 * 64 + (uint32_t)((c0 ^ ((r0 >> 1) & 3)) << 4);
    const __nv_bfloat16* gAh0 = Ah + (long long)(m0 + r0) * K + c0 * 8;
    const __nv_bfloat16* gAl0 = Al + (long long)(m0 + r0) * K + c0 * 8;
    const __nv_bfloat16* gBh0 = Bh + (long long)(n0 + r0) * K + c0 * 8;
    const __nv_bfloat16* gBl0 = Bl + (long long)(n0 + r0) * K + c0 * 8;
    const long long rstep = 64LL * K;

#define ISSUE(chv) do {                                                         \
    const long long k0_ = (long long)(chv) * 32;                                \
    const uint32_t sba_ = sb + (uint32_t)((chv) & 3) * 32768u;                  \
    cp16(sba_ + soff0,                 gAh0 + k0_);                             \
    cp16(sba_ + soff0 + 4096,          gAh0 + rstep + k0_);                     \
    cp16(sba_ + 8192 + soff0,          gAl0 + k0_);                             \
    cp16(sba_ + 8192 + soff0 + 4096,   gAl0 + rstep + k0_);                     \
    cp16(sba_ + 16384 + soff0,         gBh0 + k0_);                             \
    cp16(sba_ + 16384 + soff0 + 4096,  gBh0 + rstep + k0_);                     \
    cp16(sba_ + 24576 + soff0,         gBl0 + k0_);                             \
    cp16(sba_ + 24576 + soff0 + 4096,  gBl0 + rstep + k0_);                     \
    asm volatile("cp.async.commit_group;" ::: "memory");                        \
} while (0)

    float acc[4][4][4];
#pragma unroll
    for (int i = 0; i < 4; i++)
#pragma unroll
        for (int j = 0; j < 4; j++)
#pragma unroll
            for (int k = 0; k < 4; k++) acc[i][j][k] = 0.f;

    const int nch = K >> 5;
    ISSUE(0); ISSUE(1); ISSUE(2);

    const int arow = m0w + (lane & 15);
    const int brow = n0w + (lane & 15);

    for (int ch = 0; ch < nch; ch++) {
        asm volatile("cp.async.wait_group 2;" ::: "memory");
        __syncthreads();

        const uint32_t stb = sb + (uint32_t)(ch & 3) * 32768u;
#pragma unroll
        for (int kstep = 0; kstep < 2; kstep++) {
            const int kc = kstep * 2 + (lane >> 4);
            uint32_t aH[4][4], aL[4][4], bh[2][4], bl[2][4];
#pragma unroll
            for (int mf = 0; mf < 4; mf++) {
                const int rr = arow + mf * 16;
                const uint32_t off =
                    (uint32_t)rr * 64 + (uint32_t)((kc ^ ((rr >> 1) & 3)) << 4);
                ldsm_x4(aH[mf], stb + off);
                ldsm_x4(aL[mf], stb + 8192 + off);
            }
#pragma unroll
            for (int q = 0; q < 2; q++) {
                const int rr = brow + q * 16;
                const uint32_t off =
                    (uint32_t)rr * 64 + (uint32_t)((kc ^ ((rr >> 1) & 3)) << 4);
                ldsm_x4(bh[q], stb + 16384 + off);
                ldsm_x4(bl[q], stb + 24576 + off);
            }
#pragma unroll
            for (int mf = 0; mf < 4; mf++)
#pragma unroll
                for (int nf = 0; nf < 4; nf++) {
                    const uint32_t b0h = bh[nf >> 1][nf & 1];
                    const uint32_t b1h = bh[nf >> 1][(nf & 1) + 2];
                    const uint32_t b0l = bl[nf >> 1][nf & 1];
                    const uint32_t b1l = bl[nf >> 1][(nf & 1) + 2];
                    mma16816(acc[mf][nf], aH[mf], b0h, b1h);
                    mma16816(acc[mf][nf], aH[mf], b0l, b1l);
                    mma16816(acc[mf][nf], aL[mf], b0h, b1h);
                }
        }
        // issue into stage (ch-1)&3: fully drained before this iter's sync
        if (ch + 3 < nch) ISSUE(ch + 3);
    }
#undef ISSUE

    // ---- epilogue ----
    const int gr = lane >> 2;
    const int gc = (lane & 3) * 2;

    if (mode == 0) {
#pragma unroll
        for (int mf = 0; mf < 4; mf++)
#pragma unroll
            for (int nf = 0; nf < 4; nf++) {
                const int row = m0 + m0w + mf * 16 + gr;
                const int col = n0 + n0w + nf * 8 + gc;
                float b0 = 0.f, b1 = 0.f;
                if (bias) { b0 = bias[col]; b1 = bias[col + 1]; }
                float2 v0 = make_float2(acc[mf][nf][0] + b0, acc[mf][nf][1] + b1);
                float2 v1 = make_float2(acc[mf][nf][2] + b0, acc[mf][nf][3] + b1);
                *reinterpret_cast<float2*>(Cf + (long long)row * N + col) = v0;
                *reinterpret_cast<float2*>(Cf + (long long)(row + 8) * N + col) = v1;
            }
    } else if (mode == 3) {
        const int seg = n0 / segN;              // CTA-uniform
        const int cbase = n0 - seg * segN + n0w;
        if (seg < 2) {
            __nv_bfloat16* Dh = seg ? P1h : P0h;
            __nv_bfloat16* Dl = seg ? P1l : P0l;
#pragma unroll
            for (int mf = 0; mf < 4; mf++)
#pragma unroll
                for (int nf = 0; nf < 4; nf++) {
                    const int row = m0 + m0w + mf * 16 + gr;
                    const int col = cbase + nf * 8 + gc;
                    const float b0 = bias[n0 + n0w + nf * 8 + gc];
                    const float b1 = bias[n0 + n0w + nf * 8 + gc + 1];
#pragma unroll
                    for (int half = 0; half < 2; half++) {
                        __nv_bfloat162 hh, ll;
                        split2(acc[mf][nf][half * 2 + 0] + b0,
                               acc[mf][nf][half * 2 + 1] + b1, hh, ll);
                        const long long idx = (long long)(row + half * 8) * segN + col;
                        *reinterpret_cast<__nv_bfloat162*>(Dh + idx) = hh;
                        *reinterpret_cast<__nv_bfloat162*>(Dl + idx) = ll;
                    }
                }
        } else {
            // V: transposed VT layout, staged via smem for coalescing
            __syncthreads();
            float* tw = reinterpret_cast<float*>(smem) + wid * 2080;
#pragma unroll
            for (int mf = 0; mf < 4; mf++)
#pragma unroll
                for (int nf = 0; nf < 4; nf++) {
                    const int rl = mf * 16 + gr;
                    const int cl = nf * 8 + gc;
                    tw[cl * 65 + rl]           = acc[mf][nf][0];
                    tw[(cl + 1) * 65 + rl]     = acc[mf][nf][1];
                    tw[cl * 65 + rl + 8]       = acc[mf][nf][2];
                    tw[(cl + 1) * 65 + rl + 8] = acc[mf][nf][3];
                }
            __syncwarp();
            const int g0 = m0 + m0w;
            const long long basev =
                (long long)(g0 >> 11) * segN * 2048 + (g0 & 2047);
#pragma unroll 4
            for (int c = 0; c < 32; c++) {
                const int colg = cbase + c;
                const float bb = bias[seg * segN + colg + segN];  // n0-based
                const float v0 = tw[c * 65 + lane * 2] + bias[n0 + n0w + c] - bb + bb;
                // (bias[n0+n0w+c] is the correct concat index; simplify)
                const float vv0 = tw[c * 65 + lane * 2] + bias[n0 + n0w + c];
                const float vv1 = tw[c * 65 + lane * 2 + 1] + bias[n0 + n0w + c];
                (void)v0;
                __nv_bfloat162 hh, ll;
                split2(vv0, vv1, hh, ll);
                const long long idx = basev + (long long)colg * 2048 + lane * 2;
                *reinterpret_cast<__nv_bfloat162*>(P2h + idx) = hh;
                *reinterpret_cast<__nv_bfloat162*>(P2l + idx) = ll;
            }
        }
    } else {
        // mode 4: PV1 + build_temp fused -> T planes
        const float w1v = rw1[0], w2v = rw2[0];
#pragma unroll
        for (int mf = 0; mf < 4; mf++)
#pragma unroll
            for (int nf = 0; nf < 4; nf++) {
                const int col = n0 + n0w + nf * 8 + gc;
#pragma unroll
                for (int half = 0; half < 2; half++) {
                    const int row = m0 + m0w + mf * 16 + gr + half * 8;
                    const int grow = z * 2048 + row;
                    long long tok; int tcol; float2 res;
                    if (grow < 8192) {
                        tok = grow; tcol = col;
                        float2 yy = *reinterpret_cast<const float2*>(
                            ry + tok * 512 + col);
                        res.x = yy.x * w2v; res.y = yy.y * w2v;
                    } else {
                        tok = grow - 8192; tcol = col + 512;
                        float2 xx = *reinterpret_cast<const float2*>(
                            rx + tok * 512 + col);
                        res.x = xx.x * w1v; res.y = xx.y * w1v;
                    }
                    __nv_bfloat162 hh, ll;
                    split2(acc[mf][nf][half * 2 + 0] + res.x,
                           acc[mf][nf][half * 2 + 1] + res.y, hh, ll);
                    const long long idx = tok * 1024 + tcol;
                    *reinterpret_cast<__nv_bfloat162*>(P0h + idx) = hh;
                    *reinterpret_cast<__nv_bfloat162*>(P0l + idx) = ll;
                }
            }
    }
}

// ---------------------------------------------------------------------------
// split fp32 -> bf16 hi/lo planes (float4)
// ---------------------------------------------------------------------------
__global__ void __launch_bounds__(256)
split_f32(const float* __restrict__ src, __nv_bfloat16* __restrict__ h,
          __nv_bfloat16* __restrict__ l, long long n4)
{
    long long i = (long long)blockIdx.x * 256 + threadIdx.x;
    if (i >= n4) return;
    float4 v = reinterpret_cast<const float4*>(src)[i];
    __nv_bfloat162 h0, l0, h1, l1;
    split2(v.x, v.y, h0, l0);
    split2(v.z, v.w, h1, l1);
    uint2 hh, ll;
    hh.x = *reinterpret_cast<uint32_t*>(&h0); hh.y = *reinterpret_cast<uint32_t*>(&h1);
    ll.x = *reinterpret_cast<uint32_t*>(&l0); ll.y = *reinterpret_cast<uint32_t*>(&l1);
    reinterpret_cast<uint2*>(h)[i] = hh;
    reinterpret_cast<uint2*>(l)[i] = ll;
}

// ---------------------------------------------------------------------------
// split 3 weight matrices into one concatenated plane pair + concat biases
// ---------------------------------------------------------------------------
__global__ void __launch_bounds__(256)
split_w3(const float* __restrict__ s0, const float* __restrict__ s1,
         const float* __restrict__ s2,
         const float* __restrict__ b0, const float* __restrict__ b1,
         const float* __restrict__ b2,
         __nv_bfloat16* __restrict__ h, __nv_bfloat16* __restrict__ l,
         float* __restrict__ bcat, int rows, int K)
{
    const long long seglen = (long long)rows * K / 4;   // float4 per segment
    long long i = (long long)blockIdx.x * 256 + threadIdx.x;
    if (i < 3 * seglen) {
        const int seg = (int)(i / seglen);
        const long long off = i - (long long)seg * seglen;
        const float* s = (seg == 0) ? s0 : (seg == 1) ? s1 : s2;
        float4 v = reinterpret_cast<const float4*>(s)[off];
        __nv_bfloat162 h0, l0, h1, l1;
        split2(v.x, v.y, h0, l0);
        split2(v.z, v.w, h1, l1);
        uint2 hh, ll;
        hh.x = *reinterpret_cast<uint32_t*>(&h0); hh.y = *reinterpret_cast<uint32_t*>(&h1);
        ll.x = *reinterpret_cast<uint32_t*>(&l0); ll.y = *reinterpret_cast<uint32_t*>(&l1);
        reinterpret_cast<uint2*>(h)[i] = hh;
        reinterpret_cast<uint2*>(l)[i] = ll;
    }
    const long long t = (long long)blockIdx.x * 256 + threadIdx.x;
    if (t < 3 * rows) {
        const int seg = (int)(t / rows);
        const int off = (int)(t - seg * rows);
        bcat[t] = (seg == 0) ? b0[off] : (seg == 1) ? b1[off] : b2[off];
    }
}

// ---------------------------------------------------------------------------
// Row softmax over 2048 cols; fp32 in, split bf16 hi/lo out. Block = row.
// ---------------------------------------------------------------------------
__global__ void __launch_bounds__(256)
softmax2048(const float* __restrict__ S, __nv_bfloat16* __restrict__ Ph,
            __nv_bfloat16* __restrict__ Pl)
{
    const float* p = S + (long long)blockIdx.x * 2048;
    const int t = threadIdx.x;

    float v[8];
    {
        const float4* p4 = reinterpret_cast<const float4*>(p + t * 8);
        float4 a = p4[0], b = p4[1];
        v[0] = a.x; v[1] = a.y; v[2] = a.z; v[3] = a.w;
        v[4] = b.x; v[5] = b.y; v[6] = b.z; v[7] = b.w;
    }

    float m = v[0];
#pragma unroll
    for (int i = 1; i < 8; i++) m = fmaxf(m, v[i]);

    __shared__ float red[8];
#pragma unroll
    for (int o = 16; o > 0; o >>= 1) m = fmaxf(m, __shfl_xor_sync(0xffffffffu, m, o));
    if ((t & 31) == 0) red[t >> 5] = m;
    __syncthreads();
    if (t < 32) {
        float mm = (t < 8) ? red[t] : -3.4e38f;
#pragma unroll
        for (int o = 4; o > 0; o >>= 1) mm = fmaxf(mm, __shfl_xor_sync(0xffffffffu, mm, o));
        if (t == 0) red[0] = mm;
    }
    __syncthreads();
    m = red[0];
    __syncthreads();

    float s = 0.f;
#pragma unroll
    for (int i = 0; i < 8; i++) { v[i] = __expf(v[i] - m); s += v[i]; }
#pragma unroll
    for (int o = 16; o > 0; o >>= 1) s += __shfl_xor_sync(0xffffffffu, s, o);
    if ((t & 31) == 0) red[t >> 5] = s;
    __syncthreads();
    if (t < 32) {
        float ss = (t < 8) ? red[t] : 0.f;
#pragma unroll
        for (int o = 4; o > 0; o >>= 1) ss += __shfl_xor_sync(0xffffffffu, ss, o);
        if (t == 0) red[0] = ss;
    }
    __syncthreads();
    const float inv = 1.f / red[0];

    __nv_bfloat162* oh =
        reinterpret_cast<__nv_bfloat162*>(Ph + (long long)blockIdx.x * 2048 + t * 8);
    __nv_bfloat162* ol =
        reinterpret_cast<__nv_bfloat162*>(Pl + (long long)blockIdx.x * 2048 + t * 8);
#pragma unroll
    for (int i = 0; i < 4; i++) {
        __nv_bfloat162 hh, ll;
        split2(v[i * 2] * inv, v[i * 2 + 1] * inv, hh, ll);
        oh[i] = hh;
        ol[i] = ll;
    }
}

// ---------------------------------------------------------------------------
extern "C" void kernel_launch(void* const* d_in, const int* in_sizes, int n_in,
                              void* d_out, int out_size)
{
    (void)in_sizes; (void)n_in; (void)out_size;

    const float* x   = (const float*)d_in[0];
    const float* y   = (const float*)d_in[1];
    const float* Wq1 = (const float*)d_in[2];
    const float* bq1 = (const float*)d_in[3];
    const float* Wk1 = (const float*)d_in[4];
    const float* bk1 = (const float*)d_in[5];
    const float* Wv1 = (const float*)d_in[6];
    const float* bv1 = (const float*)d_in[7];
    const float* Wq2 = (const float*)d_in[8];
    const float* bq2 = (const float*)d_in[9];
    const float* Wk2 = (const float*)d_in[10];
    const float* bk2 = (const float*)d_in[11];
    const float* Wv2 = (const float*)d_in[12];
    const float* bv2 = (const float*)d_in[13];
    const float* w1  = (const float*)d_in[14];
    const float* w2  = (const float*)d_in[15];
    float* out = (float*)d_out;

    __nv_bfloat16 *xyh, *xyl, *w1h, *w1l, *w2h, *w2l;
    __nv_bfloat16 *Q1h, *Q1l, *K1h, *K1l, *VT1h, *VT1l, *Ph, *Pl;
    __nv_bfloat16 *Th, *Tl, *Q2h, *Q2l, *K2h, *K2l, *VT2h, *VT2l;
    float *S, *b1c, *b2c;
    cudaGetSymbolAddress((void**)&xyh, g_xyh);   cudaGetSymbolAddress((void**)&xyl, g_xyl);
    cudaGetSymbolAddress((void**)&w1h, g_w1h);   cudaGetSymbolAddress((void**)&w1l, g_w1l);
    cudaGetSymbolAddress((void**)&w2h, g_w2h);   cudaGetSymbolAddress((void**)&w2l, g_w2l);
    cudaGetSymbolAddress((void**)&b1c, g_b1);    cudaGetSymbolAddress((void**)&b2c, g_b2);
    cudaGetSymbolAddress((void**)&Q1h, g_Q1h);   cudaGetSymbolAddress((void**)&Q1l, g_Q1l);
    cudaGetSymbolAddress((void**)&K1h, g_K1h);   cudaGetSymbolAddress((void**)&K1l, g_K1l);
    cudaGetSymbolAddress((void**)&VT1h, g_VT1h); cudaGetSymbolAddress((void**)&VT1l, g_VT1l);
    cudaGetSymbolAddress((void**)&S, g_S);
    cudaGetSymbolAddress((void**)&Ph, g_Ph);     cudaGetSymbolAddress((void**)&Pl, g_Pl);
    cudaGetSymbolAddress((void**)&Th, g_Th);     cudaGetSymbolAddress((void**)&Tl, g_Tl);
    cudaGetSymbolAddress((void**)&Q2h, g_Q2h);   cudaGetSymbolAddress((void**)&Q2l, g_Q2l);
    cudaGetSymbolAddress((void**)&K2h, g_K2h);   cudaGetSymbolAddress((void**)&K2l, g_K2l);
    cudaGetSymbolAddress((void**)&VT2h, g_VT2h); cudaGetSymbolAddress((void**)&VT2l, g_VT2l);

    cudaFuncSetAttribute(gemm_bf3, cudaFuncAttributeMaxDynamicSharedMemorySize,
                         SMEM_BYTES);

    const dim3 blk(256);
    const long long HX = 8192LL * 512;
    const __nv_bfloat16* NB = nullptr;
    const float* NF = nullptr;

    // 1,2: split x,y into stacked planes
    split_f32<<<(int)((HX / 4 + 255) / 256), blk>>>(x, xyh, xyl, HX / 4);
    split_f32<<<(int)((HX / 4 + 255) / 256), blk>>>(y, xyh + HX, xyl + HX, HX / 4);
    // 3,4: split+concat weights and biases
    split_w3<<<(3 * 512 * 512 / 4 + 255) / 256, blk>>>(Wq1, Wk1, Wv1, bq1, bk1, bv1,
                                                       w1h, w1l, b1c, 512, 512);
    split_w3<<<(3 * 1024 * 1024 / 4 + 255) / 256, blk>>>(Wq2, Wk2, Wv2, bq2, bk2, bv2,
                                                         w2h, w2l, b2c, 1024, 1024);

    // 5: QKV1 fused (M=16384, N=1536, K=512), routing epilogue
    dim3 g1(1536 / 128, 16384 / 128);
    gemm_bf3<<<g1, blk, SMEM_BYTES>>>(xyh, xyl, w1h, w1l, b1c,
                                      nullptr, Q1h, Q1l, K1h, K1l, VT1h, VT1l,
                                      NF, NF, NF, NF,
                                      16384, 1536, 512, 0, 0, 0, 3, 512);

    // 6: scores1 (z=8)
    dim3 gs1(2048 / 128, 2048 / 128, 8);
    gemm_bf3<<<gs1, blk, SMEM_BYTES>>>(Q1h, Q1l, K1h, K1l, nullptr,
                                       S, nullptr, nullptr, NB ? nullptr : nullptr,
                                       nullptr, nullptr, nullptr,
                                       NF, NF, NF, NF,
                                       2048, 2048, 512,
                                       2048LL * 512, 2048LL * 512, 2048LL * 2048, 0, 0);
    // 7: softmax1
    softmax2048<<<16384, blk>>>(S, Ph, Pl);
    // 8: PV1 + build_temp fused -> T planes
    dim3 gp1(512 / 128, 2048 / 128, 8);
    gemm_bf3<<<gp1, blk, SMEM_BYTES>>>(Ph, Pl, VT1h, VT1l, nullptr,
                                       nullptr, Th, Tl, nullptr, nullptr, nullptr, nullptr,
                                       x, y, w1, w2,
                                       2048, 512, 2048,
                                       2048LL * 2048, 512LL * 2048, 0, 4, 0);

    // 9: QKV2 fused (M=8192, N=3072, K=1024)
    dim3 g2(3072 / 128, 8192 / 128);
    gemm_bf3<<<g2, blk, SMEM_BYTES>>>(Th, Tl, w2h, w2l, b2c,
                                      nullptr, Q2h, Q2l, K2h, K2l, VT2h, VT2l,
                                      NF, NF, NF, NF,
                                      8192, 3072, 1024, 0, 0, 0, 3, 1024);

    // 10: scores2 (z=4)
    dim3 gs2(2048 / 128, 2048 / 128, 4);
    gemm_bf3<<<gs2, blk, SMEM_BYTES>>>(Q2h, Q2l, K2h, K2l, nullptr,
                                       S, nullptr, nullptr, nullptr, nullptr, nullptr, nullptr,
                                       NF, NF, NF, NF,
                                       2048, 2048, 1024,
                                       2048LL * 1024, 2048LL * 1024, 2048LL * 2048, 0, 0);
    // 11: softmax2
    softmax2048<<<8192, blk>>>(S, Ph, Pl);
    // 12: PV2 -> out (fp32)
    dim3 gp2(1024 / 128, 2048 / 128, 4);
    gemm_bf3<<<gp2, blk, SMEM_BYTES>>>(Ph, Pl, VT2h, VT2l, nullptr,
                                       out, nullptr, nullptr, nullptr, nullptr, nullptr, nullptr,
                                       NF, NF, NF, NF,
                                       2048, 1024, 2048,
                                       2048LL * 2048, 1024LL * 2048, 2048LL * 1024, 0, 0);
}